// round 5
// baseline (speedup 1.0000x reference)
#include <cuda_runtime.h>
#include <math.h>

// ---------------------------------------------------------------------------
// Problem constants
// ---------------------------------------------------------------------------
#define B_   2
#define P_   4000
#define NP_  4096
#define D_   64
#define M_   512
#define NX_  432
#define NY_  496
#define HW_  (NX_ * NY_)          // 214272

#define S0_   ((size_t)B_ * 128 * HW_)
#define S2_   ((size_t)B_ * 64 * HW_)
#define OFF1_ (S0_)
#define OFF2_ (2 * S0_)
#define OFF3_ (2 * S0_ + S2_)                        // 137,134,080 floats to zero
#define OFF4_ (OFF3_ + (size_t)B_ * P_ * D_)

// Tiling
#define TILE_P 64
#define TILE_T 64
#define CPTS   512                      // points per chunk (stage-1 work unit)
#define CH_    8                        // chunks over NP_ = 4096
#define PITCH  68                       // 272B rows; conflict-free LDS.128
#define NTHR   256
#define PTILES 63                       // ceil(4000/64)
#define NB_PTC (PTILES * B_ * CH_)      // 1008 point-chunk blocks
#define NB_MEM (PTILES * B_)            // 126 memory blocks (512 = 1 chunk)
#define NB_ATT (NB_PTC + NB_MEM)        // 1134
#define NB_Z   648
#define NGRP   162                      // groups of 11: 4 zero + 7 attn
#define NB_TOT (NGRP * 11)              // 1782

// dynamic shared layout (bytes)
#define SM_PL   0                                   // 64*68*4   = 17408
#define SM_PT   17408                               // 2*64*68*4 = 34816
#define SM_TKV  52224                               // 64*8*4    =  2048
#define SM_TKI  54272                               // 64*8*4    =  2048
#define SMEM_BYTES 56320                            // 3 blocks/SM

__device__ int   g_winner[B_ * HW_];
__device__ float g_pkv[B_ * P_ * 64];               // partial top-8 vals (8 chunks x 8)
__device__ int   g_pki[B_ * P_ * 64];               // partial top-8 global point idx

// ---------------------------------------------------------------------------
__device__ __forceinline__ void cp16(void* dst, const void* src) {
    unsigned a = (unsigned)__cvta_generic_to_shared(dst);
    asm volatile("cp.async.cg.shared.global [%0], [%1], 16;" :: "r"(a), "l"(src));
}
__device__ __forceinline__ void cp_commit() {
    asm volatile("cp.async.commit_group;" ::: "memory");
}
__device__ __forceinline__ void cp_wait_all() {
    asm volatile("cp.async.wait_group 0;" ::: "memory");
}
// packed f32x2 FMA (SASS FFMA2: 2 MACs/inst)
__device__ __forceinline__ void fma2(unsigned long long& acc,
                                     unsigned long long a, unsigned long long b) {
    asm volatile("fma.rn.f32x2 %0, %1, %2, %0;" : "+l"(acc) : "l"(a), "l"(b));
}

// ---------------------------------------------------------------------------
// Core: 64 pillars x 512 candidate vectors -> per-pillar top-8 (val, global
// idx) left in s_tkv/s_tki. 8 warps; warp wy owns pillars [wy*8, wy*8+8).
// Lane tx owns candidate rows {tx, tx+32} of each 64-row tile. 8x2 microtile,
// packed-f32x2 FMA, cp.async double buffer.
// ---------------------------------------------------------------------------
__device__ __forceinline__ void attn_core(const float* __restrict__ pb,   // pillar tile base
                                          const float* __restrict__ vb,   // 512 vectors
                                          int idx_base, int pvalid, char* smem)
{
    float* s_pl  = (float*)(smem + SM_PL);
    float* s_pt  = (float*)(smem + SM_PT);
    float* s_tkv = (float*)(smem + SM_TKV);
    int*   s_tki = (int*)(smem + SM_TKI);

    const int t  = threadIdx.x;
    const int tx = t & 31;
    const int wy = t >> 5;
    const unsigned FULL = 0xffffffffu;

    s_tkv[t]       = -INFINITY;
    s_tkv[t + 256] = -INFINITY;

    // prefetch tile 0 (64 rows x 256B)
#pragma unroll
    for (int q = 0; q < 4; ++q) {
        int lin = t + q * NTHR;
        int r = lin >> 4, c = (lin & 15) << 2;
        cp16(s_pt + r * PITCH + c, vb + r * D_ + c);
    }
    cp_commit();

    // load pillar tile (zero-pad tail)
#pragma unroll
    for (int q = 0; q < 4; ++q) {
        int lin = t + q * NTHR;
        int r = lin >> 4, c = (lin & 15) << 2;
        float4 v = make_float4(0.f, 0.f, 0.f, 0.f);
        if (r < pvalid) v = *(const float4*)(pb + r * D_ + c);
        *(float4*)(s_pl + r * PITCH + c) = v;
    }
    __syncthreads();

    float vmin[8];
#pragma unroll
    for (int i = 0; i < 8; ++i) vmin[i] = -INFINITY;

    const int NT = CPTS / TILE_T;   // 8
    for (int tile = 0; tile < NT; ++tile) {
        float* buf = s_pt + (tile & 1) * (TILE_T * PITCH);
        cp_wait_all();
        __syncthreads();
        if (tile + 1 < NT) {
            float* nb = s_pt + ((tile + 1) & 1) * (TILE_T * PITCH);
            const float* src = vb + (size_t)(tile + 1) * TILE_T * D_;
#pragma unroll
            for (int q = 0; q < 4; ++q) {
                int lin = t + q * NTHR;
                int r = lin >> 4, c = (lin & 15) << 2;
                cp16(nb + r * PITCH + c, src + r * D_ + c);
            }
            cp_commit();
        }

        unsigned long long acc[8][2];
#pragma unroll
        for (int i = 0; i < 8; ++i) { acc[i][0] = 0ull; acc[i][1] = 0ull; }

        const float* prow = s_pl + (wy << 3) * PITCH;
#pragma unroll 4
        for (int dc = 0; dc < D_; dc += 4) {
            ulonglong2 xv0 = *(const ulonglong2*)(buf + tx * PITCH + dc);
            ulonglong2 xv1 = *(const ulonglong2*)(buf + (tx + 32) * PITCH + dc);
#pragma unroll
            for (int i = 0; i < 8; ++i) {
                ulonglong2 av = *(const ulonglong2*)(prow + i * PITCH + dc);
                fma2(acc[i][0], av.x, xv0.x);
                fma2(acc[i][1], av.x, xv1.x);
                fma2(acc[i][0], av.y, xv0.y);
                fma2(acc[i][1], av.y, xv1.y);
            }
        }

        // warp-private top-8 maintenance (hot path: 1 ballot per pillar)
        const int base = idx_base + tile * TILE_T;
#pragma unroll
        for (int i = 0; i < 8; ++i) {
            const int pr = (wy << 3) + i;
            float thr = vmin[i];
            float s0, s1;
            {
                unsigned long long v = acc[i][0];
                s0 = __uint_as_float((unsigned)v) +
                     __uint_as_float((unsigned)(v >> 32));
                v = acc[i][1];
                s1 = __uint_as_float((unsigned)v) +
                     __uint_as_float((unsigned)(v >> 32));
            }
            unsigned any = __ballot_sync(FULL, (s0 > thr) | (s1 > thr));
            if (any) {
                float* tv = s_tkv + pr * 8;
                int*   ti = s_tki + pr * 8;
#pragma unroll
                for (int j = 0; j < 2; ++j) {
                    float sj = j ? s1 : s0;
                    unsigned m = __ballot_sync(FULL, sj > thr);
                    while (m) {
                        int ln = __ffs(m) - 1; m &= m - 1;
                        float v = __shfl_sync(FULL, sj, ln);
                        if (v > thr) {       // warp-uniform
                            int slot = 0; float mn = tv[0];
#pragma unroll
                            for (int k = 1; k < 8; ++k) {
                                float x = tv[k];
                                if (x < mn) { mn = x; slot = k; }
                            }
                            tv[slot] = v;
                            ti[slot] = base + ln + 32 * j;
                            thr = tv[0];
#pragma unroll
                            for (int k = 1; k < 8; ++k) thr = fminf(thr, tv[k]);
                        }
                    }
                }
                vmin[i] = thr;
            }
        }
    }
    __syncwarp();
}

// ---------------------------------------------------------------------------
// Fused stage-1: point-chunk blocks + memory blocks + zero blocks interleaved
// (per 11 blocks: 4 zero, 7 attention) so DRAM-bound zeroing overlaps FMA.
// ---------------------------------------------------------------------------
__global__ void __launch_bounds__(NTHR, 3)
fused_kernel(const float* __restrict__ pillars,
             const float* __restrict__ points,
             const float* __restrict__ W,
             float* __restrict__ out)
{
    extern __shared__ char smem[];
    const int g = blockIdx.x / 11;
    const int r = blockIdx.x % 11;

    if (r < 4) {
        // ---- zero role
        const int zid = g * 4 + r;
        const int t = threadIdx.x;
        float4* o4 = (float4*)out;
        const size_t n4 = OFF3_ / 4;
        const size_t stride = (size_t)NB_Z * NTHR;
        const float4 z = make_float4(0.f, 0.f, 0.f, 0.f);
        for (size_t i = (size_t)zid * NTHR + t; i < n4; i += stride)
            __stcs(o4 + i, z);
        for (int i = zid * NTHR + t; i < B_ * HW_; i += NB_Z * NTHR)
            g_winner[i] = -1;
        return;
    }

    const int aid = g * 7 + (r - 4);
    float* s_tkv = (float*)(smem + SM_TKV);
    int*   s_tki = (int*)(smem + SM_TKI);
    const int t  = threadIdx.x;
    const int tx = t & 31;
    const int wy = t >> 5;

    if (aid < NB_PTC) {
        // ---- point-chunk role: partial top-8 -> scratch
        const int chunk = aid / (PTILES * B_);      // group same chunk for L2 reuse
        const int pid   = aid % (PTILES * B_);
        const int b     = pid / PTILES;
        const int p0    = (pid % PTILES) * TILE_P;
        const int pvalid = min(TILE_P, P_ - p0);
        const float* pb = pillars + ((size_t)b * P_ + p0) * D_;
        const float* vb = points + ((size_t)b * NP_ + (size_t)chunk * CPTS) * D_;
        attn_core(pb, vb, chunk * CPTS, pvalid, smem);

        const int bp0 = b * P_ + p0;
#pragma unroll 1
        for (int i = 0; i < 8; ++i) {
            const int pr = (wy << 3) + i;
            if (pr >= pvalid) break;
            if (tx < 8) {
                g_pkv[(size_t)(bp0 + pr) * 64 + chunk * 8 + tx] = s_tkv[pr * 8 + tx];
                g_pki[(size_t)(bp0 + pr) * 64 + chunk * 8 + tx] = s_tki[pr * 8 + tx];
            }
        }
    } else {
        // ---- memory role: M_=512 = one chunk, full epilogue here
        const int id = aid - NB_PTC;
        const int b  = id / PTILES;
        const int p0 = (id % PTILES) * TILE_P;
        const int pvalid = min(TILE_P, P_ - p0);
        const float* pb = pillars + ((size_t)b * P_ + p0) * D_;
        attn_core(pb, W, 0, pvalid, smem);

#pragma unroll 1
        for (int i = 0; i < 8; ++i) {
            const int pr = (wy << 3) + i;
            if (pr >= pvalid) break;
            float vals[8]; int id8[8];
#pragma unroll
            for (int k = 0; k < 8; ++k) {
                vals[k] = s_tkv[pr * 8 + k]; id8[k] = s_tki[pr * 8 + k];
            }
            float mx = vals[0];
#pragma unroll
            for (int k = 1; k < 8; ++k) mx = fmaxf(mx, vals[k]);
            float w[8], ssum = 0.f;
#pragma unroll
            for (int k = 0; k < 8; ++k) { w[k] = expf(vals[k] - mx); ssum += w[k]; }
            float inv = 1.f / ssum;
            float a0 = 0.f, a1 = 0.f;
#pragma unroll
            for (int k = 0; k < 8; ++k) {
                const float* vp = W + (size_t)id8[k] * D_;
                float wk = w[k] * inv;
                a0 += wk * vp[tx];
                a1 += wk * vp[tx + 32];
            }
            float* op = out + OFF4_ + ((size_t)b * P_ + p0 + pr) * D_;
            op[tx] = a0;
            op[tx + 32] = a1;
        }
    }
}

// ---------------------------------------------------------------------------
// Stage-2 merge: one warp per pillar merges 64 candidates -> top-8, softmax,
// weighted gather of point vectors, writes pos_point.
// ---------------------------------------------------------------------------
__global__ void __launch_bounds__(256)
merge_kernel(const float* __restrict__ points, float* __restrict__ out)
{
    const int w  = blockIdx.x * 8 + (threadIdx.x >> 5);
    const int tx = threadIdx.x & 31;
    if (w >= B_ * P_) return;
    const unsigned FULL = 0xffffffffu;
    const int b = w / P_;
    const float* vb = points + (size_t)b * NP_ * D_;

    float v0 = g_pkv[(size_t)w * 64 + tx];
    float v1 = g_pkv[(size_t)w * 64 + 32 + tx];
    int   i0 = g_pki[(size_t)w * 64 + tx];
    int   i1 = g_pki[(size_t)w * 64 + 32 + tx];

    float vals[8]; int ids[8];
#pragma unroll
    for (int k = 0; k < 8; ++k) {
        float m = fmaxf(v0, v1);
#pragma unroll
        for (int off = 16; off; off >>= 1)
            m = fmaxf(m, __shfl_xor_sync(FULL, m, off));
        bool hit0 = (v0 == m), hit1 = (v1 == m);
        unsigned ball = __ballot_sync(FULL, hit0 | hit1);
        int ln = __ffs(ball) - 1;
        int my = hit0 ? i0 : i1;
        int idx = __shfl_sync(FULL, my, ln);
        if (tx == ln) { if (hit0) v0 = -INFINITY; else v1 = -INFINITY; }
        vals[k] = m; ids[k] = idx;
    }

    float mx = vals[0];
#pragma unroll
    for (int k = 1; k < 8; ++k) mx = fmaxf(mx, vals[k]);
    float wt[8], ssum = 0.f;
#pragma unroll
    for (int k = 0; k < 8; ++k) { wt[k] = expf(vals[k] - mx); ssum += wt[k]; }
    float inv = 1.f / ssum;
    float a0 = 0.f, a1 = 0.f;
#pragma unroll
    for (int k = 0; k < 8; ++k) {
        const float* vp = vb + (size_t)ids[k] * D_;
        float wk = wt[k] * inv;
        a0 += wk * vp[tx];
        a1 += wk * vp[tx + 32];
    }
    float* op = out + OFF3_ + (size_t)w * D_;
    op[tx] = a0;
    op[tx + 32] = a1;
}

// duplicate indices: scatter applies updates in order -> last p wins
__global__ void winner_kernel(const int* __restrict__ idx) {
    int i = blockIdx.x * blockDim.x + threadIdx.x;
    if (i < B_ * P_) {
        int b = i / P_;
        atomicMax(&g_winner[b * HW_ + idx[i]], i - b * P_);
    }
}

__global__ void scatter_kernel(const float* __restrict__ pil,
                               const float* __restrict__ scale,
                               const int* __restrict__ idx,
                               float* out) {
    int bp = blockIdx.x;                 // 0 .. B*P-1
    int b = (bp >= P_) ? 1 : 0;
    int p = bp - b * P_;
    int col = idx[bp];
    if (g_winner[b * HW_ + col] != p) return;
    int c = threadIdx.x;                 // 0..63
    float pv = pil[(size_t)bp * D_ + c];
    float sv = scale[(size_t)bp * D_ + c];
    float qv = out[OFF3_ + (size_t)bp * D_ + c];   // pos_point
    float mv = out[OFF4_ + (size_t)bp * D_ + c];   // pos_mem
    size_t g0 = (size_t)b * 128 * HW_ + (size_t)c * HW_ + col;
    out[g0] = pv;                                   // sp[:64]
    out[g0 + (size_t)64 * HW_] = mv;                // sp[64:]
    out[OFF1_ + g0] = pv;                           // sp_point[:64]
    out[OFF1_ + g0 + (size_t)64 * HW_] = qv;        // sp_point[64:]
    out[OFF2_ + (size_t)b * 64 * HW_ + (size_t)c * HW_ + col] = sv;
}

// ---------------------------------------------------------------------------
extern "C" void kernel_launch(void* const* d_in, const int* in_sizes, int n_in,
                              void* d_out, int out_size) {
    (void)in_sizes; (void)n_in; (void)out_size;
    const float* pillars = (const float*)d_in[0];
    const float* scale   = (const float*)d_in[1];
    const float* points  = (const float*)d_in[2];
    const float* W       = (const float*)d_in[3];
    const int*   idx     = (const int*)d_in[4];
    float* out = (float*)d_out;

    cudaFuncSetAttribute(fused_kernel,
                         cudaFuncAttributeMaxDynamicSharedMemorySize, SMEM_BYTES);

    fused_kernel<<<NB_TOT, NTHR, SMEM_BYTES>>>(pillars, points, W, out);
    merge_kernel<<<(B_ * P_ + 7) / 8, 256>>>(points, out);
    winner_kernel<<<(B_ * P_ + 255) / 256, 256>>>(idx);
    scatter_kernel<<<B_ * P_, 64>>>(pillars, scale, idx, out);
}